// round 7
// baseline (speedup 1.0000x reference)
#include <cuda_runtime.h>

// Problem constants: N=1024 agents, H=64 hidden.
#define Nn 1024
#define Hh 64
#define EE (Nn * (Nn - 1))   // 1047552 edges

// Factored first layer:
//   gA[i][k] = b1[k] + sum_c emb[i][c] * W1[c][k]
//   gB[j][k] =         sum_c emb[j][c] * W1[64+c][k]
__device__ float gA[Nn * Hh];
__device__ float gB[Nn * Hh];

// ---- packed f32x2 helpers (sm_10x; only add/mul/fma exist packed) ----------
__device__ __forceinline__ float2 add2(float2 a, float2 b) {
    float2 d;
    asm("add.rn.f32x2 %0, %1, %2;"
        : "=l"(*reinterpret_cast<unsigned long long*>(&d))
        : "l"(*reinterpret_cast<const unsigned long long*>(&a)),
          "l"(*reinterpret_cast<const unsigned long long*>(&b)));
    return d;
}
__device__ __forceinline__ float2 fma2(float2 a, float2 b, float2 c) {
    float2 d;
    asm("fma.rn.f32x2 %0, %1, %2, %3;"
        : "=l"(*reinterpret_cast<unsigned long long*>(&d))
        : "l"(*reinterpret_cast<const unsigned long long*>(&a)),
          "l"(*reinterpret_cast<const unsigned long long*>(&b)),
          "l"(*reinterpret_cast<const unsigned long long*>(&c)));
    return d;
}

// ---------------------------------------------------------------------------
// Kernel 1: (a) gA/gB = emb @ [W1_top | W1_bot] with W1 staged in SMEM
// (CTAs 0..127, 8 rows each, warp-per-row); (b) the two edge_index planes,
// generated by ALL 296 CTAs (2 balanced waves) — these stores overlap the
// latency-bound GEMM and keep them out of the pair kernel's epilogue.
// ---------------------------------------------------------------------------
#define PREP_CTAS 296

__global__ void __launch_bounds__(256) prep_kernel(const float* __restrict__ emb,
                                                   const float* __restrict__ W1,
                                                   const float* __restrict__ b1,
                                                   float* __restrict__ out) {
    __shared__ float sW1[128 * 64];   // 32 KB

    const int t = threadIdx.x;

    if (blockIdx.x < 128) {
#pragma unroll
        for (int q = t; q < 2048; q += 256)
            reinterpret_cast<float4*>(sW1)[q] = reinterpret_cast<const float4*>(W1)[q];
        __syncthreads();

        const int row = blockIdx.x * 8 + (t >> 5);
        const int lane = t & 31;
        const int m = lane * 4;
        const int half = m >> 6;
        const int k = m & 63;
        const float* w1base = sW1 + half * Hh * Hh;

        float acc0 = 0.f, acc1 = 0.f, acc2 = 0.f, acc3 = 0.f;
#pragma unroll
        for (int c = 0; c < Hh; c += 4) {
            const float4 e4 = *reinterpret_cast<const float4*>(emb + row * Hh + c);
            const float4 w0 = *reinterpret_cast<const float4*>(w1base + (c + 0) * Hh + k);
            const float4 w1v = *reinterpret_cast<const float4*>(w1base + (c + 1) * Hh + k);
            const float4 w2v = *reinterpret_cast<const float4*>(w1base + (c + 2) * Hh + k);
            const float4 w3v = *reinterpret_cast<const float4*>(w1base + (c + 3) * Hh + k);
            acc0 = fmaf(e4.x, w0.x, acc0); acc0 = fmaf(e4.y, w1v.x, acc0);
            acc0 = fmaf(e4.z, w2v.x, acc0); acc0 = fmaf(e4.w, w3v.x, acc0);
            acc1 = fmaf(e4.x, w0.y, acc1); acc1 = fmaf(e4.y, w1v.y, acc1);
            acc1 = fmaf(e4.z, w2v.y, acc1); acc1 = fmaf(e4.w, w3v.y, acc1);
            acc2 = fmaf(e4.x, w0.z, acc2); acc2 = fmaf(e4.y, w1v.z, acc2);
            acc2 = fmaf(e4.z, w2v.z, acc2); acc2 = fmaf(e4.w, w3v.z, acc2);
            acc3 = fmaf(e4.x, w0.w, acc3); acc3 = fmaf(e4.y, w1v.w, acc3);
            acc3 = fmaf(e4.z, w2v.w, acc3); acc3 = fmaf(e4.w, w3v.w, acc3);
        }

        float4 o;
        if (half == 0) {
            const float4 bb = *reinterpret_cast<const float4*>(b1 + k);
            o.x = acc0 + bb.x; o.y = acc1 + bb.y; o.z = acc2 + bb.z; o.w = acc3 + bb.w;
            *reinterpret_cast<float4*>(&gA[row * Hh + k]) = o;
        } else {
            o.x = acc0; o.y = acc1; o.z = acc2; o.w = acc3;
            *reinterpret_cast<float4*>(&gB[row * Hh + k]) = o;
        }
    }

    // --- edge_index planes (all CTAs): out[e] = i, out[E+e] = j ---
    // e = i*1023 + (j - (j>i));  inverse: i = e/1023, r = e%1023, j = r + (r>=i)
    const unsigned tid = blockIdx.x * 256 + t;       // 75776 threads
    const unsigned nquads = EE / 4;                  // 261888
    for (unsigned q = tid; q < nquads; q += PREP_CTAS * 256) {
        const unsigned e0 = q * 4;
        float4 vi, vj;
        float* pi = &vi.x;
        float* pj = &vj.x;
#pragma unroll
        for (int u = 0; u < 4; u++) {
            const unsigned e = e0 + u;
            const unsigned i = e / 1023u;
            const unsigned r = e - i * 1023u;
            const unsigned j = r + (r >= i ? 1u : 0u);
            pi[u] = (float)i;
            pj[u] = (float)j;
        }
        *reinterpret_cast<float4*>(out + e0) = vi;
        *reinterpret_cast<float4*>(out + EE + e0) = vj;
    }
}

// ---------------------------------------------------------------------------
// Kernel 2: per-pair MLP. Grid 32(j) x 32(i) = 1024 CTAs, 128 threads
// (all resident; ~7 CTAs/SM). Tile 32(i) x 32(j); 2x4 micro-tile:
//   tx = t&7, ty = t>>3 (0..15);  i = i0 + ty + 16*ii (ii<2),
//   j = j0 + tx + 8*jj (jj<4)  -> 8 pairs / thread, 8 independent acc chains.
// Bank analysis (TPAD=76 words, bank = word mod 32, quad = 12*row mod 32):
//   B rows tx+8jj: quads {0,12,24,4,16,28,8,20} cover all 32 banks once;
//   A rows ty+16ii: 4 distinct ty/warp -> 4 distinct quads; W broadcast.
//   => every LDS.128 is conflict-free.
// Epilogue writes ONLY the sigmoid weight plane (index planes done in prep).
// ---------------------------------------------------------------------------
#define TSI 32
#define TSJ 32
#define TPAD 76

__global__ void __launch_bounds__(128, 10) pair_kernel(const float* __restrict__ W2,
                                                       const float* __restrict__ b2ptr,
                                                       float* __restrict__ out) {
    __shared__ float sA[TSI * TPAD];
    __shared__ float sB[TSJ * TPAD];
    __shared__ float sW2[64];

    const int t = threadIdx.x;
    const int tx = t & 7;
    const int ty = t >> 3;
    const int i0 = blockIdx.y * TSI;
    const int j0 = blockIdx.x * TSJ;

    // Cooperative tile loads: sA 512 + sB 512 float4 = 1024 / 128 threads = 8 each.
#pragma unroll
    for (int q = t; q < 1024; q += 128) {
        if (q < 512) {
            const int r = q >> 4, c4 = (q & 15) * 4;
            *reinterpret_cast<float4*>(&sA[r * TPAD + c4]) =
                *reinterpret_cast<const float4*>(&gA[(i0 + r) * Hh + c4]);
        } else {
            const int q2 = q - 512;
            const int r = q2 >> 4, c4 = (q2 & 15) * 4;
            *reinterpret_cast<float4*>(&sB[r * TPAD + c4]) =
                *reinterpret_cast<const float4*>(&gB[(j0 + r) * Hh + c4]);
        }
    }
    if (t < 64) sW2[t] = W2[t];
    __syncthreads();

    const float b2 = b2ptr[0];
    float2 acc[2][4];
#pragma unroll
    for (int ii = 0; ii < 2; ii++)
#pragma unroll
        for (int jj = 0; jj < 4; jj++)
            acc[ii][jj] = make_float2(b2, 0.f);   // fold b2 into lo half

#pragma unroll 4
    for (int k = 0; k < Hh; k += 4) {
        const float4 wq = *reinterpret_cast<const float4*>(&sW2[k]);
        const float2 w01 = *reinterpret_cast<const float2*>(&wq.x);
        const float2 w23 = *reinterpret_cast<const float2*>(&wq.z);

        float4 av[2], bv[4];
#pragma unroll
        for (int u = 0; u < 2; u++)
            av[u] = *reinterpret_cast<const float4*>(&sA[(ty + 16 * u) * TPAD + k]);
#pragma unroll
        for (int u = 0; u < 4; u++)
            bv[u] = *reinterpret_cast<const float4*>(&sB[(tx + 8 * u) * TPAD + k]);

#pragma unroll
        for (int ii = 0; ii < 2; ii++) {
            const float2 a01 = *reinterpret_cast<const float2*>(&av[ii].x);
            const float2 a23 = *reinterpret_cast<const float2*>(&av[ii].z);
#pragma unroll
            for (int jj = 0; jj < 4; jj++) {
                const float2 b01 = *reinterpret_cast<const float2*>(&bv[jj].x);
                const float2 b23 = *reinterpret_cast<const float2*>(&bv[jj].z);
                float2 t01 = add2(a01, b01);
                float2 t23 = add2(a23, b23);
                t01.x = fmaxf(t01.x, 0.f); t01.y = fmaxf(t01.y, 0.f);
                t23.x = fmaxf(t23.x, 0.f); t23.y = fmaxf(t23.y, 0.f);
                acc[ii][jj] = fma2(t01, w01, acc[ii][jj]);
                acc[ii][jj] = fma2(t23, w23, acc[ii][jj]);
            }
        }
    }

#pragma unroll
    for (int ii = 0; ii < 2; ii++) {
        const int i = i0 + ty + 16 * ii;
#pragma unroll
        for (int jj = 0; jj < 4; jj++) {
            const int j = j0 + tx + 8 * jj;
            if (j == i) continue;
            const int e = i * (Nn - 1) + j - (j > i ? 1 : 0);
            const float x = acc[ii][jj].x + acc[ii][jj].y;   // b2 already folded
            out[2 * EE + e] = 1.0f / (1.0f + __expf(-x));
        }
    }
}

extern "C" void kernel_launch(void* const* d_in, const int* in_sizes, int n_in,
                              void* d_out, int out_size) {
    const float* emb = (const float*)d_in[0];  // [1024, 64]
    const float* W1  = (const float*)d_in[1];  // [128, 64]
    const float* b1  = (const float*)d_in[2];  // [64]
    const float* W2  = (const float*)d_in[3];  // [64, 1]
    const float* b2  = (const float*)d_in[4];  // [1]
    float* out = (float*)d_out;

    prep_kernel<<<PREP_CTAS, 256>>>(emb, W1, b1, out);
    pair_kernel<<<dim3(32, 32), 128>>>(W2, b2, out);
}

// round 8
// speedup vs baseline: 1.1045x; 1.1045x over previous
#include <cuda_runtime.h>

// Problem constants: N=1024 agents, H=64 hidden.
#define Nn 1024
#define Hh 64
#define EE (Nn * (Nn - 1))   // 1047552 edges

// Factored first layer:
//   gA[i][k] = b1[k] + sum_c emb[i][c] * W1[c][k]
//   gB[j][k] =         sum_c emb[j][c] * W1[64+c][k]
__device__ float gA[Nn * Hh];
__device__ float gB[Nn * Hh];

// ---- packed f32x2 helpers (sm_10x; only add/mul/fma exist packed) ----------
__device__ __forceinline__ float2 add2(float2 a, float2 b) {
    float2 d;
    asm("add.rn.f32x2 %0, %1, %2;"
        : "=l"(*reinterpret_cast<unsigned long long*>(&d))
        : "l"(*reinterpret_cast<const unsigned long long*>(&a)),
          "l"(*reinterpret_cast<const unsigned long long*>(&b)));
    return d;
}
__device__ __forceinline__ float2 fma2(float2 a, float2 b, float2 c) {
    float2 d;
    asm("fma.rn.f32x2 %0, %1, %2, %3;"
        : "=l"(*reinterpret_cast<unsigned long long*>(&d))
        : "l"(*reinterpret_cast<const unsigned long long*>(&a)),
          "l"(*reinterpret_cast<const unsigned long long*>(&b)),
          "l"(*reinterpret_cast<const unsigned long long*>(&c)));
    return d;
}

// ---------------------------------------------------------------------------
// Kernel 1: gA/gB = emb @ [W1_top | W1_bot] with W1 staged in SMEM once per
// CTA. 128 CTAs x 256 threads; warp = one emb row, lanes cover the 128
// output cols in float4 quads. Index planes are NOT done here (pair epilogue
// proved net-cheaper in round 6 vs 7).
// ---------------------------------------------------------------------------
__global__ void __launch_bounds__(256) prep_kernel(const float* __restrict__ emb,
                                                   const float* __restrict__ W1,
                                                   const float* __restrict__ b1) {
    __shared__ float sW1[128 * 64];   // 32 KB

    const int t = threadIdx.x;
#pragma unroll
    for (int q = t; q < 2048; q += 256)
        reinterpret_cast<float4*>(sW1)[q] = reinterpret_cast<const float4*>(W1)[q];
    __syncthreads();

    const int row = blockIdx.x * 8 + (t >> 5);
    const int lane = t & 31;
    const int m = lane * 4;
    const int half = m >> 6;
    const int k = m & 63;
    const float* w1base = sW1 + half * Hh * Hh;

    float acc0 = 0.f, acc1 = 0.f, acc2 = 0.f, acc3 = 0.f;
#pragma unroll
    for (int c = 0; c < Hh; c += 4) {
        const float4 e4 = *reinterpret_cast<const float4*>(emb + row * Hh + c);
        const float4 w0 = *reinterpret_cast<const float4*>(w1base + (c + 0) * Hh + k);
        const float4 w1v = *reinterpret_cast<const float4*>(w1base + (c + 1) * Hh + k);
        const float4 w2v = *reinterpret_cast<const float4*>(w1base + (c + 2) * Hh + k);
        const float4 w3v = *reinterpret_cast<const float4*>(w1base + (c + 3) * Hh + k);
        acc0 = fmaf(e4.x, w0.x, acc0); acc0 = fmaf(e4.y, w1v.x, acc0);
        acc0 = fmaf(e4.z, w2v.x, acc0); acc0 = fmaf(e4.w, w3v.x, acc0);
        acc1 = fmaf(e4.x, w0.y, acc1); acc1 = fmaf(e4.y, w1v.y, acc1);
        acc1 = fmaf(e4.z, w2v.y, acc1); acc1 = fmaf(e4.w, w3v.y, acc1);
        acc2 = fmaf(e4.x, w0.z, acc2); acc2 = fmaf(e4.y, w1v.z, acc2);
        acc2 = fmaf(e4.z, w2v.z, acc2); acc2 = fmaf(e4.w, w3v.z, acc2);
        acc3 = fmaf(e4.x, w0.w, acc3); acc3 = fmaf(e4.y, w1v.w, acc3);
        acc3 = fmaf(e4.z, w2v.w, acc3); acc3 = fmaf(e4.w, w3v.w, acc3);
    }

    float4 o;
    if (half == 0) {
        const float4 bb = *reinterpret_cast<const float4*>(b1 + k);
        o.x = acc0 + bb.x; o.y = acc1 + bb.y; o.z = acc2 + bb.z; o.w = acc3 + bb.w;
        *reinterpret_cast<float4*>(&gA[row * Hh + k]) = o;
    } else {
        o.x = acc0; o.y = acc1; o.z = acc2; o.w = acc3;
        *reinterpret_cast<float4*>(&gB[row * Hh + k]) = o;
    }
}

// ---------------------------------------------------------------------------
// Kernel 2: per-pair MLP, REGISTER-PIPELINED k-loop.
// Grid 32x32 = 1024 CTAs, 128 threads, __launch_bounds__(128,7):
//   7 CTAs/SM x 148 = 1036 slots -> the whole grid is ONE wave (no tail),
//   28 warps/SM, and a 73-reg budget for double-buffered operands.
// Tile 32(i) x 32(j); 2x4 micro-tile (tx=t&7, ty=t>>3):
//   i = i0 + ty + 16*ii (ii<2),  j = j0 + tx + 8*jj (jj<4).
// Mainloop: prefetch chunk k+4's 6 A/B LDS.128 into `nxt` registers, then do
// chunk k's 64 packed-math instrs on `cur` -> load-to-use distance ~70 issue
// slots, hiding LDS lat 29 and the cross-pipe ADD2->FMNMX->FMA2 chain.
// Bank analysis (TPAD=76, quad-bank = 12*row mod 32): B rows tx+8jj give
// {0,12,24,4,16,28,8,20} (all distinct); A rows broadcast per 8-lane phase,
// 4 distinct quads per warp -> all LDS.128 conflict-free.
// Epilogue writes all three planes (i, j, sigmoid weight).
// ---------------------------------------------------------------------------
#define TSI 32
#define TSJ 32
#define TPAD 76

__global__ void __launch_bounds__(128, 7) pair_kernel(const float* __restrict__ W2,
                                                      const float* __restrict__ b2ptr,
                                                      float* __restrict__ out) {
    __shared__ float sA[TSI * TPAD];
    __shared__ float sB[TSJ * TPAD];
    __shared__ float sW2[64];

    const int t = threadIdx.x;
    const int tx = t & 7;
    const int ty = t >> 3;
    const int i0 = blockIdx.y * TSI;
    const int j0 = blockIdx.x * TSJ;

    // Cooperative tile loads: sA 512 + sB 512 float4 = 1024 / 128 threads = 8 each.
#pragma unroll
    for (int q = t; q < 1024; q += 128) {
        if (q < 512) {
            const int r = q >> 4, c4 = (q & 15) * 4;
            *reinterpret_cast<float4*>(&sA[r * TPAD + c4]) =
                *reinterpret_cast<const float4*>(&gA[(i0 + r) * Hh + c4]);
        } else {
            const int q2 = q - 512;
            const int r = q2 >> 4, c4 = (q2 & 15) * 4;
            *reinterpret_cast<float4*>(&sB[r * TPAD + c4]) =
                *reinterpret_cast<const float4*>(&gB[(j0 + r) * Hh + c4]);
        }
    }
    if (t < 64) sW2[t] = W2[t];
    __syncthreads();

    const float b2 = b2ptr[0];
    float2 acc[2][4];
#pragma unroll
    for (int ii = 0; ii < 2; ii++)
#pragma unroll
        for (int jj = 0; jj < 4; jj++)
            acc[ii][jj] = make_float2(b2, 0.f);   // fold b2 into lo half

    const float* aRow0 = &sA[ty * TPAD];
    const float* aRow1 = &sA[(ty + 16) * TPAD];
    const float* bRow0 = &sB[tx * TPAD];
    const float* bRow1 = &sB[(tx + 8) * TPAD];
    const float* bRow2 = &sB[(tx + 16) * TPAD];
    const float* bRow3 = &sB[(tx + 24) * TPAD];

    float4 curA0 = *reinterpret_cast<const float4*>(aRow0);
    float4 curA1 = *reinterpret_cast<const float4*>(aRow1);
    float4 curB0 = *reinterpret_cast<const float4*>(bRow0);
    float4 curB1 = *reinterpret_cast<const float4*>(bRow1);
    float4 curB2 = *reinterpret_cast<const float4*>(bRow2);
    float4 curB3 = *reinterpret_cast<const float4*>(bRow3);

#pragma unroll
    for (int kc = 0; kc < 16; kc++) {
        const int k = kc * 4;
        const float4 wq = *reinterpret_cast<const float4*>(&sW2[k]);
        const float2 w01 = *reinterpret_cast<const float2*>(&wq.x);
        const float2 w23 = *reinterpret_cast<const float2*>(&wq.z);

        // Prefetch next chunk while computing this one.
        float4 nxtA0, nxtA1, nxtB0, nxtB1, nxtB2, nxtB3;
        if (kc < 15) {
            const int kn = k + 4;
            nxtA0 = *reinterpret_cast<const float4*>(aRow0 + kn);
            nxtA1 = *reinterpret_cast<const float4*>(aRow1 + kn);
            nxtB0 = *reinterpret_cast<const float4*>(bRow0 + kn);
            nxtB1 = *reinterpret_cast<const float4*>(bRow1 + kn);
            nxtB2 = *reinterpret_cast<const float4*>(bRow2 + kn);
            nxtB3 = *reinterpret_cast<const float4*>(bRow3 + kn);
        }

        const float4 av[2] = {curA0, curA1};
        const float4 bv[4] = {curB0, curB1, curB2, curB3};
#pragma unroll
        for (int ii = 0; ii < 2; ii++) {
            const float2 a01 = *reinterpret_cast<const float2*>(&av[ii].x);
            const float2 a23 = *reinterpret_cast<const float2*>(&av[ii].z);
#pragma unroll
            for (int jj = 0; jj < 4; jj++) {
                const float2 b01 = *reinterpret_cast<const float2*>(&bv[jj].x);
                const float2 b23 = *reinterpret_cast<const float2*>(&bv[jj].z);
                float2 t01 = add2(a01, b01);
                float2 t23 = add2(a23, b23);
                t01.x = fmaxf(t01.x, 0.f); t01.y = fmaxf(t01.y, 0.f);
                t23.x = fmaxf(t23.x, 0.f); t23.y = fmaxf(t23.y, 0.f);
                acc[ii][jj] = fma2(t01, w01, acc[ii][jj]);
                acc[ii][jj] = fma2(t23, w23, acc[ii][jj]);
            }
        }

        if (kc < 15) {
            curA0 = nxtA0; curA1 = nxtA1;
            curB0 = nxtB0; curB1 = nxtB1; curB2 = nxtB2; curB3 = nxtB3;
        }
    }

#pragma unroll
    for (int ii = 0; ii < 2; ii++) {
        const int i = i0 + ty + 16 * ii;
#pragma unroll
        for (int jj = 0; jj < 4; jj++) {
            const int j = j0 + tx + 8 * jj;
            if (j == i) continue;
            const int e = i * (Nn - 1) + j - (j > i ? 1 : 0);
            const float x = acc[ii][jj].x + acc[ii][jj].y;   // b2 already folded
            out[e] = (float)i;
            out[EE + e] = (float)j;
            out[2 * EE + e] = 1.0f / (1.0f + __expf(-x));
        }
    }
}

extern "C" void kernel_launch(void* const* d_in, const int* in_sizes, int n_in,
                              void* d_out, int out_size) {
    const float* emb = (const float*)d_in[0];  // [1024, 64]
    const float* W1  = (const float*)d_in[1];  // [128, 64]
    const float* b1  = (const float*)d_in[2];  // [64]
    const float* W2  = (const float*)d_in[3];  // [64, 1]
    const float* b2  = (const float*)d_in[4];  // [1]
    float* out = (float*)d_out;

    prep_kernel<<<128, 256>>>(emb, W1, b1);
    pair_kernel<<<dim3(32, 32), 128>>>(W2, b2, out);
}